// round 15
// baseline (speedup 1.0000x reference)
#include <cuda_runtime.h>
#include <cuda_fp16.h>

#define NN 50000
#define NE 800000
#define C  128
#define NG 128
#define OC 16
#define NBLK 196        // ceil(50000/256)
#define GEMM_BLKS 782   // ceil(50000/64)
#define FILL_BLKS 3125  // ceil(800000/256)
#define TOT_BLKS (GEMM_BLKS + FILL_BLKS)   // 3907
#define XS_STRIDE 136   // padded half stride (conflict-free)

// Scratch (static device globals — no allocation in kernel_launch)
__device__ __align__(16) __half g_Ah[NN * C];   // hs = (X@W)*dis, fp16 (12.8MB, L2-resident)
__device__ __align__(16) __half g_X2h[NN * C];  // layer-2 input, fp16
__device__ __align__(16) float g_pool[NG * C];
__device__ float g_dis[NN];
__device__ int   g_src[NE];
__device__ int   g_dst[NE];
__device__ int   g_bat[NN];
__device__ int   g_cnt_i[NN];
__device__ int   g_cursor[NN];
__device__ int   g_rs[NN + 1];
__device__ int   g_col[NE];
__device__ int   g_gcnt[NG];
__device__ int   g_bsum[NBLK];
__device__ int   g_boff[NBLK];
__device__ int   g_done;
__device__ int   g_flag;
__device__ int   g_is64;

// launch 0
__global__ void k_init(const int* __restrict__ ei_raw) {
    int i = blockIdx.x * blockDim.x + threadIdx.x;
    if (i == 0) {
        int hi_or = 0, lo_ok = 1;
        for (int j = 0; j < 256; j++) {
            hi_or |= ei_raw[2 * j + 1];
            int lo = ei_raw[2 * j];
            lo_ok &= (lo >= 0 && lo < NN) ? 1 : 0;
        }
        g_is64 = (hi_or == 0 && lo_ok) ? 1 : 0;
        g_done = 0;
        g_flag = 0;
    }
    if (i < NN) g_cnt_i[i] = 0;
    if (i < NG * C) g_pool[i] = 0.0f;
    if (i < NG) g_gcnt[i] = 0;
}

// launch 1
__global__ void k_convert_hist(const void* __restrict__ ei_raw, const void* __restrict__ bat_raw) {
    int i = blockIdx.x * blockDim.x + threadIdx.x;
    const bool is64 = (g_is64 != 0);
    if (i < NE) {
        int s, d;
        if (is64) {
            const long long* p = (const long long*)ei_raw;
            s = (int)p[i]; d = (int)p[NE + i];
        } else {
            const int* p = (const int*)ei_raw;
            s = p[i]; d = p[NE + i];
        }
        g_src[i] = s; g_dst[i] = d;
        atomicAdd(&g_cnt_i[d], 1);
    }
    if (i < NN) {
        int b = is64 ? (int)((const long long*)bat_raw)[i] : ((const int*)bat_raw)[i];
        g_bat[i] = b;
        atomicAdd(&g_gcnt[b], 1);
    }
}

// launch 2: full CSR prefix work (196 co-resident blocks)
__global__ void k_scanAB() {
    int t = threadIdx.x;
    int i = blockIdx.x * blockDim.x + t;
    int c = (i < NN) ? g_cnt_i[i] : 0;
    if (i < NN) g_dis[i] = rsqrtf((float)(c + 1));

    int r = c;
#pragma unroll
    for (int off = 16; off > 0; off >>= 1)
        r += __shfl_down_sync(0xffffffffu, r, off);
    __shared__ int ws[8];
    int lane = t & 31, w = t >> 5;
    if (lane == 0) ws[w] = r;
    __syncthreads();
    __shared__ int isLast;
    if (t == 0) {
        int s = 0;
#pragma unroll
        for (int j = 0; j < 8; j++) s += ws[j];
        g_bsum[blockIdx.x] = s;
        __threadfence();
        isLast = (atomicAdd(&g_done, 1) == (int)gridDim.x - 1) ? 1 : 0;
    }
    __syncthreads();
    if (isLast) {
        __shared__ int s[256];
        int v = (t < NBLK) ? g_bsum[t] : 0;
        s[t] = v;
        __syncthreads();
#pragma unroll
        for (int off = 1; off < 256; off <<= 1) {
            int x = (t >= off) ? s[t - off] : 0;
            __syncthreads();
            s[t] += x;
            __syncthreads();
        }
        if (t < NBLK) g_boff[t] = s[t] - v;
        __threadfence();
        __syncthreads();
        if (t == 0) atomicExch(&g_flag, 1);
    } else {
        if (t == 0) { while (atomicAdd(&g_flag, 0) == 0) {} }
    }
    __syncthreads();
    __threadfence();

    int incl = c;
#pragma unroll
    for (int off = 1; off < 32; off <<= 1) {
        int n = __shfl_up_sync(0xffffffffu, incl, off);
        if (lane >= off) incl += n;
    }
    __shared__ int wsum[8], woff[8];
    if (lane == 31) wsum[w] = incl;
    __syncthreads();
    if (t == 0) {
        int run = 0;
#pragma unroll
        for (int j = 0; j < 8; j++) { woff[j] = run; run += wsum[j]; }
    }
    __syncthreads();
    if (i < NN) {
        int pre = (incl - c) + woff[w] + __ldcg(&g_boff[blockIdx.x]);
        g_rs[i] = pre;
        g_cursor[i] = pre;
    }
    if (i == 0) g_rs[NN] = NE;
}

// HMMA gemm core: outh = fp16( (X @ W) * dis[row] ).
// BM=64, 256 threads = 8 warps tiled 4(M) x 2(N). m16n8k16 f16*f16+f32.
// smem: Xh[64][136] fp16, Wh[128][136] fp16 (row-major [k][n], B via ldmatrix.x4.trans)
template<bool XHALF>
__device__ __forceinline__ void gemm_body(
        const void* __restrict__ X, const float* __restrict__ W,
        const float* __restrict__ dis, __half* __restrict__ outh, int bm) {
    extern __shared__ __half smh[];
    __half* Xh = smh;                       // 64*136 halves
    __half* Wh = smh + 64 * XS_STRIDE;      // 128*136 halves
    const int tid = threadIdx.x;

    // Stage X tile (64 x 128) as fp16
#pragma unroll
    for (int t = 0; t < 8; t++) {
        int idx = tid + t * 256;            // 0..2047
        int row = idx >> 5, c4 = idx & 31;  // c4: 4-col group
        int gr = bm + row;
        uint2 u = make_uint2(0u, 0u);
        if (gr < NN) {
            if (XHALF) {
                u = ((const uint2*)X)[gr * 32 + c4];
            } else {
                float4 v = ((const float4*)X)[gr * 32 + c4];
                __half2 h0 = __floats2half2_rn(v.x, v.y);
                __half2 h1 = __floats2half2_rn(v.z, v.w);
                u.x = *reinterpret_cast<unsigned int*>(&h0);
                u.y = *reinterpret_cast<unsigned int*>(&h1);
            }
        }
        *(uint2*)(Xh + row * XS_STRIDE + c4 * 4) = u;
    }
    // Stage W (128 x 128) as fp16, row-major [k][n]
#pragma unroll
    for (int t = 0; t < 16; t++) {
        int idx = tid + t * 256;            // 0..4095
        int k = idx >> 5, c4 = idx & 31;
        float4 v = ((const float4*)W)[idx];
        __half2 h0 = __floats2half2_rn(v.x, v.y);
        __half2 h1 = __floats2half2_rn(v.z, v.w);
        uint2 u;
        u.x = *reinterpret_cast<unsigned int*>(&h0);
        u.y = *reinterpret_cast<unsigned int*>(&h1);
        *(uint2*)(Wh + k * XS_STRIDE + c4 * 4) = u;
    }
    __syncthreads();

    const int lane = tid & 31, wid = tid >> 5;
    const int warpM = wid >> 1, warpN = wid & 1;
    const int g = lane >> 2, tig = lane & 3;

    float acc[8][4];
#pragma unroll
    for (int nt = 0; nt < 8; nt++)
#pragma unroll
        for (int j = 0; j < 4; j++) acc[nt][j] = 0.f;

    const int xr0 = (warpM * 16 + g) * XS_STRIDE;
    const int xr1 = xr0 + 8 * XS_STRIDE;
    unsigned wbase = (unsigned)__cvta_generic_to_shared(Wh);
    // ldmatrix.x4 lane addressing: lanes 0-15 -> rows k0+lane, col nt2*16;
    // lanes 16-31 -> rows k0+(lane-16), col nt2*16+8  (both + warpN*64)
    const int lrow = lane & 15;
    const int lcol = warpN * 64 + ((lane >> 4) << 3);

#pragma unroll
    for (int kk = 0; kk < 8; kk++) {
        int k0 = kk * 16;
        unsigned a0 = *(const unsigned*)(Xh + xr0 + k0 + 2 * tig);
        unsigned a1 = *(const unsigned*)(Xh + xr1 + k0 + 2 * tig);
        unsigned a2 = *(const unsigned*)(Xh + xr0 + k0 + 2 * tig + 8);
        unsigned a3 = *(const unsigned*)(Xh + xr1 + k0 + 2 * tig + 8);
        unsigned baddr = wbase +
            (unsigned)(((k0 + lrow) * XS_STRIDE + lcol) * 2);
#pragma unroll
        for (int nt2 = 0; nt2 < 4; nt2++) {
            unsigned b0, b1, b2, b3;
            asm volatile("ldmatrix.sync.aligned.m8n8.x4.trans.shared.b16 {%0,%1,%2,%3}, [%4];"
                         : "=r"(b0), "=r"(b1), "=r"(b2), "=r"(b3)
                         : "r"(baddr + nt2 * 32));
            int nt = 2 * nt2;
            asm volatile("mma.sync.aligned.m16n8k16.row.col.f32.f16.f16.f32 "
                         "{%0,%1,%2,%3}, {%4,%5,%6,%7}, {%8,%9}, {%0,%1,%2,%3};"
                         : "+f"(acc[nt][0]), "+f"(acc[nt][1]),
                           "+f"(acc[nt][2]), "+f"(acc[nt][3])
                         : "r"(a0), "r"(a1), "r"(a2), "r"(a3), "r"(b0), "r"(b1));
            asm volatile("mma.sync.aligned.m16n8k16.row.col.f32.f16.f16.f32 "
                         "{%0,%1,%2,%3}, {%4,%5,%6,%7}, {%8,%9}, {%0,%1,%2,%3};"
                         : "+f"(acc[nt + 1][0]), "+f"(acc[nt + 1][1]),
                           "+f"(acc[nt + 1][2]), "+f"(acc[nt + 1][3])
                         : "r"(a0), "r"(a1), "r"(a2), "r"(a3), "r"(b2), "r"(b3));
        }
    }

    // Epilogue: scale by dis, write half2
    int row0 = bm + warpM * 16 + g;
    int row1 = row0 + 8;
    float s0 = (row0 < NN) ? dis[row0] : 0.f;
    float s1 = (row1 < NN) ? dis[row1] : 0.f;
#pragma unroll
    for (int nt = 0; nt < 8; nt++) {
        int col = warpN * 64 + nt * 8 + 2 * tig;
        if (row0 < NN) {
            __half2 h = __floats2half2_rn(acc[nt][0] * s0, acc[nt][1] * s0);
            *(__half2*)(outh + row0 * C + col) = h;
        }
        if (row1 < NN) {
            __half2 h = __floats2half2_rn(acc[nt][2] * s1, acc[nt][3] * s1);
            *(__half2*)(outh + row1 * C + col) = h;
        }
    }
}

// launch 3: heterogeneous, INTERLEAVED roles — blockIdx % 5 == 0 -> gemm (782 blocks),
// else CSR fill (3125 blocks). Interleaving keeps both populations co-resident so the
// L2-atomic fill hides under the tensor-bound gemm instead of running after it.
__global__ __launch_bounds__(256) void k_gemm_fill(
        const float* __restrict__ X, const float* __restrict__ W,
        const float* __restrict__ dis, __half* __restrict__ outh) {
    int bid = blockIdx.x;
    if (bid % 5 != 0) {
        int fill_id = bid - bid / 5 - 1;          // bijective 0..3124
        int e = fill_id * 256 + threadIdx.x;
        if (e < NE) {
            int d = g_dst[e];
            int off = atomicAdd(&g_cursor[d], 1);
            g_col[off] = g_src[e];
        }
        return;
    }
    gemm_body<false>(X, W, dis, outh, (bid / 5) * 64);
}

// launch 5: layer-2 gemm (fp16 X)
__global__ __launch_bounds__(256) void k_gemm2(
        const __half* __restrict__ X, const float* __restrict__ W,
        const float* __restrict__ dis, __half* __restrict__ outh) {
    gemm_body<true>(X, W, dis, outh, blockIdx.x * 64);
}

// fp16 gather core: fp32 acc = hs[d] + sum hs[col[e]]; lane owns 4 channels (uint2)
__device__ __forceinline__ float4 agg_row_h(const __half* __restrict__ hs, int d, int lane) {
    const uint2* h = (const uint2*)hs;
    uint2 vs = h[d * 32 + lane];
    float2 f0 = __half22float2(*reinterpret_cast<__half2*>(&vs.x));
    float2 f1 = __half22float2(*reinterpret_cast<__half2*>(&vs.y));
    float4 acc = make_float4(f0.x, f0.y, f1.x, f1.y);
    int e = g_rs[d], end = g_rs[d + 1];
    for (; e + 4 <= end; e += 4) {
        int s0 = g_col[e], s1 = g_col[e + 1], s2 = g_col[e + 2], s3 = g_col[e + 3];
        uint2 v0 = h[s0 * 32 + lane];
        uint2 v1 = h[s1 * 32 + lane];
        uint2 v2 = h[s2 * 32 + lane];
        uint2 v3 = h[s3 * 32 + lane];
        float2 a0 = __half22float2(*reinterpret_cast<__half2*>(&v0.x));
        float2 b0 = __half22float2(*reinterpret_cast<__half2*>(&v0.y));
        float2 a1 = __half22float2(*reinterpret_cast<__half2*>(&v1.x));
        float2 b1 = __half22float2(*reinterpret_cast<__half2*>(&v1.y));
        float2 a2 = __half22float2(*reinterpret_cast<__half2*>(&v2.x));
        float2 b2 = __half22float2(*reinterpret_cast<__half2*>(&v2.y));
        float2 a3 = __half22float2(*reinterpret_cast<__half2*>(&v3.x));
        float2 b3 = __half22float2(*reinterpret_cast<__half2*>(&v3.y));
        acc.x += (a0.x + a1.x) + (a2.x + a3.x);
        acc.y += (a0.y + a1.y) + (a2.y + a3.y);
        acc.z += (b0.x + b1.x) + (b2.x + b3.x);
        acc.w += (b0.y + b1.y) + (b2.y + b3.y);
    }
    for (; e < end; e++) {
        int s = g_col[e];
        uint2 v = h[s * 32 + lane];
        float2 a = __half22float2(*reinterpret_cast<__half2*>(&v.x));
        float2 b = __half22float2(*reinterpret_cast<__half2*>(&v.y));
        acc.x += a.x; acc.y += a.y; acc.z += b.x; acc.w += b.y;
    }
    return acc;
}

// launch 4: layer-1 aggregation + relu -> fp16 X2
__global__ void k_agg_relu(const __half* __restrict__ hs, const float* __restrict__ bias,
                           __half* __restrict__ outh) {
    int d = blockIdx.x * (blockDim.x >> 5) + (threadIdx.x >> 5);
    int lane = threadIdx.x & 31;
    if (d >= NN) return;
    float4 acc = agg_row_h(hs, d, lane);
    float sc = g_dis[d];
    float4 bb = ((const float4*)bias)[lane];
    __half2 h0 = __floats2half2_rn(fmaxf(fmaf(sc, acc.x, bb.x), 0.f),
                                   fmaxf(fmaf(sc, acc.y, bb.y), 0.f));
    __half2 h1 = __floats2half2_rn(fmaxf(fmaf(sc, acc.z, bb.z), 0.f),
                                   fmaxf(fmaf(sc, acc.w, bb.w), 0.f));
    uint2 u;
    u.x = *reinterpret_cast<unsigned int*>(&h0);
    u.y = *reinterpret_cast<unsigned int*>(&h1);
    ((uint2*)outh)[d * 32 + lane] = u;
}

// launch 6: layer-2 aggregation + relu + mean-pool scatter
__global__ void k_agg_pool(const __half* __restrict__ hs, const float* __restrict__ bias) {
    int d = blockIdx.x * (blockDim.x >> 5) + (threadIdx.x >> 5);
    int lane = threadIdx.x & 31;
    if (d >= NN) return;
    float4 acc = agg_row_h(hs, d, lane);
    float sc = g_dis[d];
    float4 bb = ((const float4*)bias)[lane];
    float4 o;
    o.x = fmaxf(fmaf(sc, acc.x, bb.x), 0.f);
    o.y = fmaxf(fmaf(sc, acc.y, bb.y), 0.f);
    o.z = fmaxf(fmaf(sc, acc.z, bb.z), 0.f);
    o.w = fmaxf(fmaf(sc, acc.w, bb.w), 0.f);
    int g = g_bat[d];
    float* p = g_pool + g * C + lane * 4;
    atomicAdd(p + 0, o.x);
    atomicAdd(p + 1, o.y);
    atomicAdd(p + 2, o.z);
    atomicAdd(p + 3, o.w);
}

// launch 7: FC + log_softmax
__global__ void k_fc(const float* __restrict__ Wfc, const float* __restrict__ bfc,
                     float* __restrict__ out) {
    __shared__ float Wf[C * OC];
    int t = threadIdx.x;
    for (int i = t; i < C * OC; i += 128) Wf[i] = Wfc[i];
    __syncthreads();

    float inv = 1.0f / fmaxf((float)g_gcnt[t], 1.0f);
    float acc[OC];
#pragma unroll
    for (int j = 0; j < OC; j++) acc[j] = bfc[j];
    for (int k = 0; k < C; k++) {
        float p = g_pool[t * C + k] * inv;
#pragma unroll
        for (int j = 0; j < OC; j++) acc[j] += p * Wf[k * OC + j];
    }
    float m = acc[0];
#pragma unroll
    for (int j = 1; j < OC; j++) m = fmaxf(m, acc[j]);
    float sum = 0.f;
#pragma unroll
    for (int j = 0; j < OC; j++) sum += expf(acc[j] - m);
    float lse = m + logf(sum);
#pragma unroll
    for (int j = 0; j < OC; j++) out[t * OC + j] = acc[j] - lse;
}

extern "C" void kernel_launch(void* const* d_in, const int* in_sizes, int n_in,
                              void* d_out, int out_size) {
    const float* x     = (const float*)d_in[0];
    const void*  ei    = d_in[1];
    const void*  batch = d_in[2];
    const float* W1    = (const float*)d_in[3];
    const float* b1    = (const float*)d_in[4];
    const float* W2    = (const float*)d_in[5];
    const float* b2    = (const float*)d_in[6];
    const float* Wfc   = (const float*)d_in[7];
    const float* bfc   = (const float*)d_in[8];
    float* out = (float*)d_out;

    __half *Ah, *X2h;
    float *dis;
    cudaGetSymbolAddress((void**)&Ah,  g_Ah);
    cudaGetSymbolAddress((void**)&X2h, g_X2h);
    cudaGetSymbolAddress((void**)&dis, g_dis);

    size_t smem = (size_t)(64 + 128) * XS_STRIDE * sizeof(__half);   // 52224 B
    cudaFuncSetAttribute(k_gemm_fill, cudaFuncAttributeMaxDynamicSharedMemorySize, (int)smem);
    cudaFuncSetAttribute(k_gemm2, cudaFuncAttributeMaxDynamicSharedMemorySize, (int)smem);

    k_init<<<NBLK, 256>>>((const int*)ei);                    // 0
    k_convert_hist<<<(NE + 255) / 256, 256>>>(ei, batch);     // 1
    k_scanAB<<<NBLK, 256>>>();                                // 2

    // Layer 1: HMMA gemm + CSR fill, interleaved roles
    k_gemm_fill<<<TOT_BLKS, 256, smem>>>(x, W1, dis, Ah);     // 3 <- ncu
    k_agg_relu<<<(NN + 7) / 8, 256>>>(Ah, b1, X2h);           // 4

    // Layer 2
    k_gemm2<<<GEMM_BLKS, 256, smem>>>(X2h, W2, dis, Ah);      // 5
    k_agg_pool<<<(NN + 7) / 8, 256>>>(Ah, b2);                // 6

    // Head
    k_fc<<<1, 128>>>(Wfc, bfc, out);                          // 7
}

// round 16
// speedup vs baseline: 1.0119x; 1.0119x over previous
#include <cuda_runtime.h>
#include <cuda_fp16.h>

#define NN 50000
#define NE 800000
#define C  128
#define NG 128
#define OC 16
#define NBLK 196        // ceil(50000/256)
#define GEMM_TILES 782  // ceil(50000/64)
#define PGEMM 296       // persistent gemm blocks = 148 SMs * 2 CTAs
#define FILL_BLKS 3125  // ceil(800000/256)
#define XS_STRIDE 136   // padded half stride (conflict-free)

// Scratch (static device globals — no allocation in kernel_launch)
__device__ __align__(16) __half g_Ah[NN * C];   // hs = (X@W)*dis, fp16 (12.8MB, L2-resident)
__device__ __align__(16) __half g_X2h[NN * C];  // layer-2 input, fp16
__device__ __align__(16) float g_pool[NG * C];
__device__ float g_dis[NN];
__device__ int   g_bat[NN];
__device__ int   g_cnt_i[NN];
__device__ int   g_cursor[NN];
__device__ int   g_rs[NN + 1];
__device__ int   g_col[NE];
__device__ int   g_gcnt[NG];
__device__ int   g_bsum[NBLK];
__device__ int   g_boff[NBLK];
__device__ int   g_done;
__device__ int   g_flag;
__device__ int   g_is64;

// launch 0: zero counters + dtype detect
__global__ void k_init(const int* __restrict__ ei_raw) {
    int i = blockIdx.x * blockDim.x + threadIdx.x;
    if (i == 0) {
        int hi_or = 0, lo_ok = 1;
        for (int j = 0; j < 256; j++) {
            hi_or |= ei_raw[2 * j + 1];
            int lo = ei_raw[2 * j];
            lo_ok &= (lo >= 0 && lo < NN) ? 1 : 0;
        }
        g_is64 = (hi_or == 0 && lo_ok) ? 1 : 0;
        g_done = 0;
        g_flag = 0;
    }
    if (i < NN) g_cnt_i[i] = 0;
    if (i < NG * C) g_pool[i] = 0.0f;
    if (i < NG) g_gcnt[i] = 0;
}

// launch 1: in-degree histogram straight from the edge buffer
__global__ void k_hist(const void* __restrict__ ei_raw) {
    int i = blockIdx.x * blockDim.x + threadIdx.x;
    if (i < NE) {
        int d = (g_is64 != 0) ? (int)((const long long*)ei_raw)[NE + i]
                              : ((const int*)ei_raw)[NE + i];
        atomicAdd(&g_cnt_i[d], 1);
    }
}

// launch 2: CSR prefix work + batch conversion (196 co-resident blocks)
__global__ void k_scanAB(const void* __restrict__ bat_raw) {
    int t = threadIdx.x;
    int i = blockIdx.x * blockDim.x + t;
    int c = (i < NN) ? g_cnt_i[i] : 0;
    if (i < NN) {
        g_dis[i] = rsqrtf((float)(c + 1));
        int b = (g_is64 != 0) ? (int)((const long long*)bat_raw)[i]
                              : ((const int*)bat_raw)[i];
        g_bat[i] = b;
        atomicAdd(&g_gcnt[b], 1);
    }

    int r = c;
#pragma unroll
    for (int off = 16; off > 0; off >>= 1)
        r += __shfl_down_sync(0xffffffffu, r, off);
    __shared__ int ws[8];
    int lane = t & 31, w = t >> 5;
    if (lane == 0) ws[w] = r;
    __syncthreads();
    __shared__ int isLast;
    if (t == 0) {
        int s = 0;
#pragma unroll
        for (int j = 0; j < 8; j++) s += ws[j];
        g_bsum[blockIdx.x] = s;
        __threadfence();
        isLast = (atomicAdd(&g_done, 1) == (int)gridDim.x - 1) ? 1 : 0;
    }
    __syncthreads();
    if (isLast) {
        __shared__ int s[256];
        int v = (t < NBLK) ? g_bsum[t] : 0;
        s[t] = v;
        __syncthreads();
#pragma unroll
        for (int off = 1; off < 256; off <<= 1) {
            int x = (t >= off) ? s[t - off] : 0;
            __syncthreads();
            s[t] += x;
            __syncthreads();
        }
        if (t < NBLK) g_boff[t] = s[t] - v;
        __threadfence();
        __syncthreads();
        if (t == 0) atomicExch(&g_flag, 1);
    } else {
        if (t == 0) { while (atomicAdd(&g_flag, 0) == 0) {} }
    }
    __syncthreads();
    __threadfence();

    int incl = c;
#pragma unroll
    for (int off = 1; off < 32; off <<= 1) {
        int n = __shfl_up_sync(0xffffffffu, incl, off);
        if (lane >= off) incl += n;
    }
    __shared__ int wsum[8], woff[8];
    if (lane == 31) wsum[w] = incl;
    __syncthreads();
    if (t == 0) {
        int run = 0;
#pragma unroll
        for (int j = 0; j < 8; j++) { woff[j] = run; run += wsum[j]; }
    }
    __syncthreads();
    if (i < NN) {
        int pre = (incl - c) + woff[w] + __ldcg(&g_boff[blockIdx.x]);
        g_rs[i] = pre;
        g_cursor[i] = pre;
    }
    if (i == 0) g_rs[NN] = NE;
}

// Persistent HMMA gemm: stage W ONCE, grid-stride over X tiles.
// BM=64, 256 threads = 8 warps tiled 4(M) x 2(N). m16n8k16 f16*f16+f32.
template<bool XHALF>
__device__ __forceinline__ void gemm_persistent(
        const void* __restrict__ X, const float* __restrict__ W,
        const float* __restrict__ dis, __half* __restrict__ outh,
        int startTile, int strideTiles) {
    extern __shared__ __half smh[];
    __half* Xh = smh;                       // 64*136 halves
    __half* Wh = smh + 64 * XS_STRIDE;      // 128*136 halves
    const int tid = threadIdx.x;

    // Stage W (128 x 128) as fp16, row-major [k][n] — ONCE per block
#pragma unroll
    for (int t = 0; t < 16; t++) {
        int idx = tid + t * 256;
        int k = idx >> 5, c4 = idx & 31;
        float4 v = ((const float4*)W)[idx];
        __half2 h0 = __floats2half2_rn(v.x, v.y);
        __half2 h1 = __floats2half2_rn(v.z, v.w);
        uint2 u;
        u.x = *reinterpret_cast<unsigned int*>(&h0);
        u.y = *reinterpret_cast<unsigned int*>(&h1);
        *(uint2*)(Wh + k * XS_STRIDE + c4 * 4) = u;
    }

    const int lane = tid & 31, wid = tid >> 5;
    const int warpM = wid >> 1, warpN = wid & 1;
    const int g = lane >> 2, tig = lane & 3;
    const int xr0 = (warpM * 16 + g) * XS_STRIDE;
    const int xr1 = xr0 + 8 * XS_STRIDE;
    unsigned wbase = (unsigned)__cvta_generic_to_shared(Wh);
    const int lrow = lane & 15;
    const int lcol = warpN * 64 + ((lane >> 4) << 3);

    for (int tile = startTile; tile < GEMM_TILES; tile += strideTiles) {
        const int bm = tile * 64;
        __syncthreads();   // Xh safe to overwrite (also orders W staging on iter 0)

        // Stage X tile (64 x 128) as fp16
#pragma unroll
        for (int t = 0; t < 8; t++) {
            int idx = tid + t * 256;
            int row = idx >> 5, c4 = idx & 31;
            int gr = bm + row;
            uint2 u = make_uint2(0u, 0u);
            if (gr < NN) {
                if (XHALF) {
                    u = ((const uint2*)X)[gr * 32 + c4];
                } else {
                    float4 v = ((const float4*)X)[gr * 32 + c4];
                    __half2 h0 = __floats2half2_rn(v.x, v.y);
                    __half2 h1 = __floats2half2_rn(v.z, v.w);
                    u.x = *reinterpret_cast<unsigned int*>(&h0);
                    u.y = *reinterpret_cast<unsigned int*>(&h1);
                }
            }
            *(uint2*)(Xh + row * XS_STRIDE + c4 * 4) = u;
        }
        __syncthreads();

        float acc[8][4];
#pragma unroll
        for (int nt = 0; nt < 8; nt++)
#pragma unroll
            for (int j = 0; j < 4; j++) acc[nt][j] = 0.f;

#pragma unroll
        for (int kk = 0; kk < 8; kk++) {
            int k0 = kk * 16;
            unsigned a0 = *(const unsigned*)(Xh + xr0 + k0 + 2 * tig);
            unsigned a1 = *(const unsigned*)(Xh + xr1 + k0 + 2 * tig);
            unsigned a2 = *(const unsigned*)(Xh + xr0 + k0 + 2 * tig + 8);
            unsigned a3 = *(const unsigned*)(Xh + xr1 + k0 + 2 * tig + 8);
            unsigned baddr = wbase + (unsigned)(((k0 + lrow) * XS_STRIDE + lcol) * 2);
#pragma unroll
            for (int nt2 = 0; nt2 < 4; nt2++) {
                unsigned b0, b1, b2, b3;
                asm volatile("ldmatrix.sync.aligned.m8n8.x4.trans.shared.b16 {%0,%1,%2,%3}, [%4];"
                             : "=r"(b0), "=r"(b1), "=r"(b2), "=r"(b3)
                             : "r"(baddr + nt2 * 32));
                int nt = 2 * nt2;
                asm volatile("mma.sync.aligned.m16n8k16.row.col.f32.f16.f16.f32 "
                             "{%0,%1,%2,%3}, {%4,%5,%6,%7}, {%8,%9}, {%0,%1,%2,%3};"
                             : "+f"(acc[nt][0]), "+f"(acc[nt][1]),
                               "+f"(acc[nt][2]), "+f"(acc[nt][3])
                             : "r"(a0), "r"(a1), "r"(a2), "r"(a3), "r"(b0), "r"(b1));
                asm volatile("mma.sync.aligned.m16n8k16.row.col.f32.f16.f16.f32 "
                             "{%0,%1,%2,%3}, {%4,%5,%6,%7}, {%8,%9}, {%0,%1,%2,%3};"
                             : "+f"(acc[nt + 1][0]), "+f"(acc[nt + 1][1]),
                               "+f"(acc[nt + 1][2]), "+f"(acc[nt + 1][3])
                             : "r"(a0), "r"(a1), "r"(a2), "r"(a3), "r"(b2), "r"(b3));
            }
        }

        // Epilogue: scale by dis, write half2
        int row0 = bm + warpM * 16 + g;
        int row1 = row0 + 8;
        float s0 = (row0 < NN) ? dis[row0] : 0.f;
        float s1 = (row1 < NN) ? dis[row1] : 0.f;
#pragma unroll
        for (int nt = 0; nt < 8; nt++) {
            int col = warpN * 64 + nt * 8 + 2 * tig;
            if (row0 < NN) {
                __half2 h = __floats2half2_rn(acc[nt][0] * s0, acc[nt][1] * s0);
                *(__half2*)(outh + row0 * C + col) = h;
            }
            if (row1 < NN) {
                __half2 h = __floats2half2_rn(acc[nt][2] * s1, acc[nt][3] * s1);
                *(__half2*)(outh + row1 * C + col) = h;
            }
        }
    }
}

// launch 3: blocks [0,PGEMM) persistent gemm layer 1; blocks [PGEMM, PGEMM+FILL_BLKS) CSR fill.
__global__ __launch_bounds__(256) void k_gemm_fill(
        const float* __restrict__ X, const float* __restrict__ W,
        const float* __restrict__ dis, __half* __restrict__ outh,
        const void* __restrict__ ei_raw) {
    if (blockIdx.x >= PGEMM) {
        int e = (blockIdx.x - PGEMM) * 256 + threadIdx.x;
        if (e < NE) {
            int s, d;
            if (g_is64 != 0) {
                const long long* p = (const long long*)ei_raw;
                s = (int)p[e]; d = (int)p[NE + e];
            } else {
                const int* p = (const int*)ei_raw;
                s = p[e]; d = p[NE + e];
            }
            int off = atomicAdd(&g_cursor[d], 1);
            g_col[off] = s;
        }
        return;
    }
    gemm_persistent<false>(X, W, dis, outh, blockIdx.x, PGEMM);
}

// launch 5: layer-2 persistent gemm (fp16 X)
__global__ __launch_bounds__(256) void k_gemm2(
        const __half* __restrict__ X, const float* __restrict__ W,
        const float* __restrict__ dis, __half* __restrict__ outh) {
    gemm_persistent<true>(X, W, dis, outh, blockIdx.x, PGEMM);
}

// fp16 gather core: fp32 acc = hs[d] + sum hs[col[e]]; lane owns 4 channels (uint2)
__device__ __forceinline__ float4 agg_row_h(const __half* __restrict__ hs, int d, int lane) {
    const uint2* h = (const uint2*)hs;
    uint2 vs = h[d * 32 + lane];
    float2 f0 = __half22float2(*reinterpret_cast<__half2*>(&vs.x));
    float2 f1 = __half22float2(*reinterpret_cast<__half2*>(&vs.y));
    float4 acc = make_float4(f0.x, f0.y, f1.x, f1.y);
    int e = g_rs[d], end = g_rs[d + 1];
    for (; e + 4 <= end; e += 4) {
        int s0 = g_col[e], s1 = g_col[e + 1], s2 = g_col[e + 2], s3 = g_col[e + 3];
        uint2 v0 = h[s0 * 32 + lane];
        uint2 v1 = h[s1 * 32 + lane];
        uint2 v2 = h[s2 * 32 + lane];
        uint2 v3 = h[s3 * 32 + lane];
        float2 a0 = __half22float2(*reinterpret_cast<__half2*>(&v0.x));
        float2 b0 = __half22float2(*reinterpret_cast<__half2*>(&v0.y));
        float2 a1 = __half22float2(*reinterpret_cast<__half2*>(&v1.x));
        float2 b1 = __half22float2(*reinterpret_cast<__half2*>(&v1.y));
        float2 a2 = __half22float2(*reinterpret_cast<__half2*>(&v2.x));
        float2 b2 = __half22float2(*reinterpret_cast<__half2*>(&v2.y));
        float2 a3 = __half22float2(*reinterpret_cast<__half2*>(&v3.x));
        float2 b3 = __half22float2(*reinterpret_cast<__half2*>(&v3.y));
        acc.x += (a0.x + a1.x) + (a2.x + a3.x);
        acc.y += (a0.y + a1.y) + (a2.y + a3.y);
        acc.z += (b0.x + b1.x) + (b2.x + b3.x);
        acc.w += (b0.y + b1.y) + (b2.y + b3.y);
    }
    for (; e < end; e++) {
        int s = g_col[e];
        uint2 v = h[s * 32 + lane];
        float2 a = __half22float2(*reinterpret_cast<__half2*>(&v.x));
        float2 b = __half22float2(*reinterpret_cast<__half2*>(&v.y));
        acc.x += a.x; acc.y += a.y; acc.z += b.x; acc.w += b.y;
    }
    return acc;
}

// launch 4: layer-1 aggregation + relu -> fp16 X2
__global__ void k_agg_relu(const __half* __restrict__ hs, const float* __restrict__ bias,
                           __half* __restrict__ outh) {
    int d = blockIdx.x * (blockDim.x >> 5) + (threadIdx.x >> 5);
    int lane = threadIdx.x & 31;
    if (d >= NN) return;
    float4 acc = agg_row_h(hs, d, lane);
    float sc = g_dis[d];
    float4 bb = ((const float4*)bias)[lane];
    __half2 h0 = __floats2half2_rn(fmaxf(fmaf(sc, acc.x, bb.x), 0.f),
                                   fmaxf(fmaf(sc, acc.y, bb.y), 0.f));
    __half2 h1 = __floats2half2_rn(fmaxf(fmaf(sc, acc.z, bb.z), 0.f),
                                   fmaxf(fmaf(sc, acc.w, bb.w), 0.f));
    uint2 u;
    u.x = *reinterpret_cast<unsigned int*>(&h0);
    u.y = *reinterpret_cast<unsigned int*>(&h1);
    ((uint2*)outh)[d * 32 + lane] = u;
}

// launch 6: layer-2 aggregation + relu + mean-pool scatter
__global__ void k_agg_pool(const __half* __restrict__ hs, const float* __restrict__ bias) {
    int d = blockIdx.x * (blockDim.x >> 5) + (threadIdx.x >> 5);
    int lane = threadIdx.x & 31;
    if (d >= NN) return;
    float4 acc = agg_row_h(hs, d, lane);
    float sc = g_dis[d];
    float4 bb = ((const float4*)bias)[lane];
    float4 o;
    o.x = fmaxf(fmaf(sc, acc.x, bb.x), 0.f);
    o.y = fmaxf(fmaf(sc, acc.y, bb.y), 0.f);
    o.z = fmaxf(fmaf(sc, acc.z, bb.z), 0.f);
    o.w = fmaxf(fmaf(sc, acc.w, bb.w), 0.f);
    int g = g_bat[d];
    float* p = g_pool + g * C + lane * 4;
    atomicAdd(p + 0, o.x);
    atomicAdd(p + 1, o.y);
    atomicAdd(p + 2, o.z);
    atomicAdd(p + 3, o.w);
}

// launch 7: FC + log_softmax
__global__ void k_fc(const float* __restrict__ Wfc, const float* __restrict__ bfc,
                     float* __restrict__ out) {
    __shared__ float Wf[C * OC];
    int t = threadIdx.x;
    for (int i = t; i < C * OC; i += 128) Wf[i] = Wfc[i];
    __syncthreads();

    float inv = 1.0f / fmaxf((float)g_gcnt[t], 1.0f);
    float acc[OC];
#pragma unroll
    for (int j = 0; j < OC; j++) acc[j] = bfc[j];
    for (int k = 0; k < C; k++) {
        float p = g_pool[t * C + k] * inv;
#pragma unroll
        for (int j = 0; j < OC; j++) acc[j] += p * Wf[k * OC + j];
    }
    float m = acc[0];
#pragma unroll
    for (int j = 1; j < OC; j++) m = fmaxf(m, acc[j]);
    float sum = 0.f;
#pragma unroll
    for (int j = 0; j < OC; j++) sum += expf(acc[j] - m);
    float lse = m + logf(sum);
#pragma unroll
    for (int j = 0; j < OC; j++) out[t * OC + j] = acc[j] - lse;
}

extern "C" void kernel_launch(void* const* d_in, const int* in_sizes, int n_in,
                              void* d_out, int out_size) {
    const float* x     = (const float*)d_in[0];
    const void*  ei    = d_in[1];
    const void*  batch = d_in[2];
    const float* W1    = (const float*)d_in[3];
    const float* b1    = (const float*)d_in[4];
    const float* W2    = (const float*)d_in[5];
    const float* b2    = (const float*)d_in[6];
    const float* Wfc   = (const float*)d_in[7];
    const float* bfc   = (const float*)d_in[8];
    float* out = (float*)d_out;

    __half *Ah, *X2h;
    float *dis;
    cudaGetSymbolAddress((void**)&Ah,  g_Ah);
    cudaGetSymbolAddress((void**)&X2h, g_X2h);
    cudaGetSymbolAddress((void**)&dis, g_dis);

    size_t smem = (size_t)(64 + 128) * XS_STRIDE * sizeof(__half);   // 52224 B
    cudaFuncSetAttribute(k_gemm_fill, cudaFuncAttributeMaxDynamicSharedMemorySize, (int)smem);
    cudaFuncSetAttribute(k_gemm2, cudaFuncAttributeMaxDynamicSharedMemorySize, (int)smem);

    k_init<<<NBLK, 256>>>((const int*)ei);                    // 0
    k_hist<<<(NE + 255) / 256, 256>>>(ei);                    // 1
    k_scanAB<<<NBLK, 256>>>(batch);                           // 2

    // Layer 1: persistent HMMA gemm + CSR fill
    k_gemm_fill<<<PGEMM + FILL_BLKS, 256, smem>>>(x, W1, dis, Ah, ei); // 3 <- ncu
    k_agg_relu<<<(NN + 7) / 8, 256>>>(Ah, b1, X2h);           // 4

    // Layer 2
    k_gemm2<<<PGEMM, 256, smem>>>(X2h, W2, dis, Ah);          // 5
    k_agg_pool<<<(NN + 7) / 8, 256>>>(Ah, b2);                // 6

    // Head
    k_fc<<<1, 128>>>(Wfc, bfc, out);                          // 7
}

// round 17
// speedup vs baseline: 1.0138x; 1.0018x over previous
#include <cuda_runtime.h>
#include <cuda_fp16.h>

#define NN 50000
#define NE 800000
#define C  128
#define NG 128
#define OC 16
#define NBLK 196        // ceil(50000/256)
#define GEMM_TILES 782  // ceil(50000/64)
#define PGEMM 296       // persistent gemm blocks = 148 SMs * 2 CTAs
#define FILL_BLKS 1563  // ceil(800000/512), 2 edges per thread
#define XS_STRIDE 136   // padded half stride (conflict-free)

// Scratch (static device globals — no allocation in kernel_launch)
__device__ __align__(16) __half g_Ah[NN * C];   // hs = (X@W)*dis, fp16 (12.8MB, L2-resident)
__device__ __align__(16) __half g_X2h[NN * C];  // layer-2 input, fp16
__device__ __align__(16) float g_pool[NG * C];
__device__ float g_dis[NN];
__device__ int   g_bat[NN];
__device__ int   g_cnt_i[NN];
__device__ int   g_cursor[NN];
__device__ int   g_rs[NN + 1];
__device__ int   g_col[NE];
__device__ int   g_gcnt[NG];
__device__ int   g_bsum[NBLK];
__device__ int   g_boff[NBLK];
__device__ int   g_sync[3];     // 0: hist barrier, 1: scan ticket, 2: boff flag
__device__ int   g_is64;

// launch 0: zero counters + dtype detect
__global__ void k_init(const int* __restrict__ ei_raw) {
    int i = blockIdx.x * blockDim.x + threadIdx.x;
    if (i == 0) {
        int hi_or = 0, lo_ok = 1;
        for (int j = 0; j < 256; j++) {
            hi_or |= ei_raw[2 * j + 1];
            int lo = ei_raw[2 * j];
            lo_ok &= (lo >= 0 && lo < NN) ? 1 : 0;
        }
        g_is64 = (hi_or == 0 && lo_ok) ? 1 : 0;
        g_sync[0] = 0; g_sync[1] = 0; g_sync[2] = 0;
    }
    if (i < NN) g_cnt_i[i] = 0;
    if (i < NG * C) g_pool[i] = 0.0f;
    if (i < NG) g_gcnt[i] = 0;
}

// launch 1: hist + grid barrier + CSR prefix + batch conversion (196 co-resident blocks)
__global__ void k_scan_all(const void* __restrict__ ei_raw, const void* __restrict__ bat_raw) {
    int t = threadIdx.x;
    const bool is64 = (g_is64 != 0);

    // Phase H: in-degree histogram, grid-stride (16 edges/thread)
    for (int e = blockIdx.x * 256 + t; e < NE; e += NBLK * 256) {
        int d = is64 ? (int)((const long long*)ei_raw)[NE + e]
                     : ((const int*)ei_raw)[NE + e];
        atomicAdd(&g_cnt_i[d], 1);
    }
    __threadfence();
    __syncthreads();
    // full grid barrier (all 196 blocks co-resident)
    if (t == 0) {
        atomicAdd(&g_sync[0], 1);
        while (atomicAdd(&g_sync[0], 0) < NBLK) {}
    }
    __syncthreads();
    __threadfence();

    // Phase S: dis, batch, per-block sums, scan
    int i = blockIdx.x * blockDim.x + t;
    int c = (i < NN) ? g_cnt_i[i] : 0;
    if (i < NN) {
        g_dis[i] = rsqrtf((float)(c + 1));
        int b = is64 ? (int)((const long long*)bat_raw)[i]
                     : ((const int*)bat_raw)[i];
        g_bat[i] = b;
        atomicAdd(&g_gcnt[b], 1);
    }

    int r = c;
#pragma unroll
    for (int off = 16; off > 0; off >>= 1)
        r += __shfl_down_sync(0xffffffffu, r, off);
    __shared__ int ws[8];
    int lane = t & 31, w = t >> 5;
    if (lane == 0) ws[w] = r;
    __syncthreads();
    __shared__ int isLast;
    if (t == 0) {
        int s = 0;
#pragma unroll
        for (int j = 0; j < 8; j++) s += ws[j];
        g_bsum[blockIdx.x] = s;
        __threadfence();
        isLast = (atomicAdd(&g_sync[1], 1) == NBLK - 1) ? 1 : 0;
    }
    __syncthreads();
    if (isLast) {
        __shared__ int s[256];
        int v = (t < NBLK) ? g_bsum[t] : 0;
        s[t] = v;
        __syncthreads();
#pragma unroll
        for (int off = 1; off < 256; off <<= 1) {
            int x = (t >= off) ? s[t - off] : 0;
            __syncthreads();
            s[t] += x;
            __syncthreads();
        }
        if (t < NBLK) g_boff[t] = s[t] - v;
        __threadfence();
        __syncthreads();
        if (t == 0) atomicExch(&g_sync[2], 1);
    } else {
        if (t == 0) { while (atomicAdd(&g_sync[2], 0) == 0) {} }
    }
    __syncthreads();
    __threadfence();

    int incl = c;
#pragma unroll
    for (int off = 1; off < 32; off <<= 1) {
        int n = __shfl_up_sync(0xffffffffu, incl, off);
        if (lane >= off) incl += n;
    }
    __shared__ int wsum[8], woff[8];
    if (lane == 31) wsum[w] = incl;
    __syncthreads();
    if (t == 0) {
        int run = 0;
#pragma unroll
        for (int j = 0; j < 8; j++) { woff[j] = run; run += wsum[j]; }
    }
    __syncthreads();
    if (i < NN) {
        int pre = (incl - c) + woff[w] + __ldcg(&g_boff[blockIdx.x]);
        g_rs[i] = pre;
        g_cursor[i] = pre;
    }
    if (i == 0) g_rs[NN] = NE;
}

// Prefetch one X tile (64x128) into 8 uint2 regs (fp16-packed)
template<bool XHALF>
__device__ __forceinline__ void prefetch_x(const void* __restrict__ X, int bm, int tid,
                                           uint2* r) {
#pragma unroll
    for (int t = 0; t < 8; t++) {
        int idx = tid + t * 256;
        int row = idx >> 5, c4 = idx & 31;
        int gr = bm + row;
        uint2 u = make_uint2(0u, 0u);
        if (gr < NN) {
            if (XHALF) {
                u = ((const uint2*)X)[gr * 32 + c4];
            } else {
                float4 v = ((const float4*)X)[gr * 32 + c4];
                __half2 h0 = __floats2half2_rn(v.x, v.y);
                __half2 h1 = __floats2half2_rn(v.z, v.w);
                u.x = *reinterpret_cast<unsigned int*>(&h0);
                u.y = *reinterpret_cast<unsigned int*>(&h1);
            }
        }
        r[t] = u;
    }
}

// Persistent HMMA gemm, double-buffered X: stage W once, prefetch tile t+1 while computing t.
template<bool XHALF>
__device__ __forceinline__ void gemm_persistent(
        const void* __restrict__ X, const float* __restrict__ W,
        const float* __restrict__ dis, __half* __restrict__ outh,
        int startTile, int strideTiles) {
    extern __shared__ __half smh[];
    __half* Wh  = smh;                          // 128*136 halves
    __half* Xh0 = smh + 128 * XS_STRIDE;        // 64*136
    __half* Xh1 = Xh0 + 64 * XS_STRIDE;         // 64*136
    const int tid = threadIdx.x;

    // Stage W (128 x 128) as fp16, row-major [k][n] — ONCE per block
#pragma unroll
    for (int t = 0; t < 16; t++) {
        int idx = tid + t * 256;
        int k = idx >> 5, c4 = idx & 31;
        float4 v = ((const float4*)W)[idx];
        __half2 h0 = __floats2half2_rn(v.x, v.y);
        __half2 h1 = __floats2half2_rn(v.z, v.w);
        uint2 u;
        u.x = *reinterpret_cast<unsigned int*>(&h0);
        u.y = *reinterpret_cast<unsigned int*>(&h1);
        *(uint2*)(Wh + k * XS_STRIDE + c4 * 4) = u;
    }

    const int lane = tid & 31, wid = tid >> 5;
    const int warpM = wid >> 1, warpN = wid & 1;
    const int g = lane >> 2, tig = lane & 3;
    const int xr0 = (warpM * 16 + g) * XS_STRIDE;
    const int xr1 = xr0 + 8 * XS_STRIDE;
    unsigned wbase = (unsigned)__cvta_generic_to_shared(Wh);
    const int lrow = lane & 15;
    const int lcol = warpN * 64 + ((lane >> 4) << 3);

    uint2 r[8];
    prefetch_x<XHALF>(X, startTile * 64, tid, r);
    int buf = 0;

    for (int tile = startTile; tile < GEMM_TILES; tile += strideTiles) {
        const int bm = tile * 64;
        __half* Xc = buf ? Xh1 : Xh0;
        // store prefetched regs into current buffer
#pragma unroll
        for (int t = 0; t < 8; t++) {
            int idx = tid + t * 256;
            int row = idx >> 5, c4 = idx & 31;
            *(uint2*)(Xc + row * XS_STRIDE + c4 * 4) = r[t];
        }
        __syncthreads();   // stores (and W on iter 0) visible; prev compute done

        int nxt = tile + strideTiles;
        if (nxt < GEMM_TILES) prefetch_x<XHALF>(X, nxt * 64, tid, r);

        float acc[8][4];
#pragma unroll
        for (int nt = 0; nt < 8; nt++)
#pragma unroll
            for (int j = 0; j < 4; j++) acc[nt][j] = 0.f;

        const int xb0 = xr0, xb1 = xr1;
#pragma unroll
        for (int kk = 0; kk < 8; kk++) {
            int k0 = kk * 16;
            unsigned a0 = *(const unsigned*)(Xc + xb0 + k0 + 2 * tig);
            unsigned a1 = *(const unsigned*)(Xc + xb1 + k0 + 2 * tig);
            unsigned a2 = *(const unsigned*)(Xc + xb0 + k0 + 2 * tig + 8);
            unsigned a3 = *(const unsigned*)(Xc + xb1 + k0 + 2 * tig + 8);
            unsigned baddr = wbase + (unsigned)(((k0 + lrow) * XS_STRIDE + lcol) * 2);
#pragma unroll
            for (int nt2 = 0; nt2 < 4; nt2++) {
                unsigned b0, b1, b2, b3;
                asm volatile("ldmatrix.sync.aligned.m8n8.x4.trans.shared.b16 {%0,%1,%2,%3}, [%4];"
                             : "=r"(b0), "=r"(b1), "=r"(b2), "=r"(b3)
                             : "r"(baddr + nt2 * 32));
                int nt = 2 * nt2;
                asm volatile("mma.sync.aligned.m16n8k16.row.col.f32.f16.f16.f32 "
                             "{%0,%1,%2,%3}, {%4,%5,%6,%7}, {%8,%9}, {%0,%1,%2,%3};"
                             : "+f"(acc[nt][0]), "+f"(acc[nt][1]),
                               "+f"(acc[nt][2]), "+f"(acc[nt][3])
                             : "r"(a0), "r"(a1), "r"(a2), "r"(a3), "r"(b0), "r"(b1));
                asm volatile("mma.sync.aligned.m16n8k16.row.col.f32.f16.f16.f32 "
                             "{%0,%1,%2,%3}, {%4,%5,%6,%7}, {%8,%9}, {%0,%1,%2,%3};"
                             : "+f"(acc[nt + 1][0]), "+f"(acc[nt + 1][1]),
                               "+f"(acc[nt + 1][2]), "+f"(acc[nt + 1][3])
                             : "r"(a0), "r"(a1), "r"(a2), "r"(a3), "r"(b2), "r"(b3));
            }
        }

        int row0 = bm + warpM * 16 + g;
        int row1 = row0 + 8;
        float s0 = (row0 < NN) ? dis[row0] : 0.f;
        float s1 = (row1 < NN) ? dis[row1] : 0.f;
#pragma unroll
        for (int nt = 0; nt < 8; nt++) {
            int col = warpN * 64 + nt * 8 + 2 * tig;
            if (row0 < NN) {
                __half2 h = __floats2half2_rn(acc[nt][0] * s0, acc[nt][1] * s0);
                *(__half2*)(outh + row0 * C + col) = h;
            }
            if (row1 < NN) {
                __half2 h = __floats2half2_rn(acc[nt][2] * s1, acc[nt][3] * s1);
                *(__half2*)(outh + row1 * C + col) = h;
            }
        }
        buf ^= 1;
    }
}

// launch 2: blocks [0,PGEMM) persistent gemm layer 1; rest CSR fill (2 edges/thread).
__global__ __launch_bounds__(256) void k_gemm_fill(
        const float* __restrict__ X, const float* __restrict__ W,
        const float* __restrict__ dis, __half* __restrict__ outh,
        const void* __restrict__ ei_raw) {
    if (blockIdx.x >= PGEMM) {
        int e = ((blockIdx.x - PGEMM) * 256 + threadIdx.x) * 2;
        if (e < NE) {
            int s0, d0, s1, d1;
            if (g_is64 != 0) {
                const long long* p = (const long long*)ei_raw;
                longlong2 sv = *(const longlong2*)(p + e);
                longlong2 dv = *(const longlong2*)(p + NE + e);
                s0 = (int)sv.x; s1 = (int)sv.y;
                d0 = (int)dv.x; d1 = (int)dv.y;
            } else {
                const int* p = (const int*)ei_raw;
                int2 sv = *(const int2*)(p + e);
                int2 dv = *(const int2*)(p + NE + e);
                s0 = sv.x; s1 = sv.y;
                d0 = dv.x; d1 = dv.y;
            }
            g_col[atomicAdd(&g_cursor[d0], 1)] = s0;
            g_col[atomicAdd(&g_cursor[d1], 1)] = s1;
        }
        return;
    }
    gemm_persistent<false>(X, W, dis, outh, blockIdx.x, PGEMM);
}

// launch 4: layer-2 persistent gemm (fp16 X)
__global__ __launch_bounds__(256) void k_gemm2(
        const __half* __restrict__ X, const float* __restrict__ W,
        const float* __restrict__ dis, __half* __restrict__ outh) {
    gemm_persistent<true>(X, W, dis, outh, blockIdx.x, PGEMM);
}

// fp16 gather core: fp32 acc = hs[d] + sum hs[col[e]]; lane owns 4 channels (uint2)
__device__ __forceinline__ float4 agg_row_h(const __half* __restrict__ hs, int d, int lane) {
    const uint2* h = (const uint2*)hs;
    uint2 vs = h[d * 32 + lane];
    float2 f0 = __half22float2(*reinterpret_cast<__half2*>(&vs.x));
    float2 f1 = __half22float2(*reinterpret_cast<__half2*>(&vs.y));
    float4 acc = make_float4(f0.x, f0.y, f1.x, f1.y);
    int e = g_rs[d], end = g_rs[d + 1];
    for (; e + 4 <= end; e += 4) {
        int s0 = g_col[e], s1 = g_col[e + 1], s2 = g_col[e + 2], s3 = g_col[e + 3];
        uint2 v0 = h[s0 * 32 + lane];
        uint2 v1 = h[s1 * 32 + lane];
        uint2 v2 = h[s2 * 32 + lane];
        uint2 v3 = h[s3 * 32 + lane];
        float2 a0 = __half22float2(*reinterpret_cast<__half2*>(&v0.x));
        float2 b0 = __half22float2(*reinterpret_cast<__half2*>(&v0.y));
        float2 a1 = __half22float2(*reinterpret_cast<__half2*>(&v1.x));
        float2 b1 = __half22float2(*reinterpret_cast<__half2*>(&v1.y));
        float2 a2 = __half22float2(*reinterpret_cast<__half2*>(&v2.x));
        float2 b2 = __half22float2(*reinterpret_cast<__half2*>(&v2.y));
        float2 a3 = __half22float2(*reinterpret_cast<__half2*>(&v3.x));
        float2 b3 = __half22float2(*reinterpret_cast<__half2*>(&v3.y));
        acc.x += (a0.x + a1.x) + (a2.x + a3.x);
        acc.y += (a0.y + a1.y) + (a2.y + a3.y);
        acc.z += (b0.x + b1.x) + (b2.x + b3.x);
        acc.w += (b0.y + b1.y) + (b2.y + b3.y);
    }
    for (; e < end; e++) {
        int s = g_col[e];
        uint2 v = h[s * 32 + lane];
        float2 a = __half22float2(*reinterpret_cast<__half2*>(&v.x));
        float2 b = __half22float2(*reinterpret_cast<__half2*>(&v.y));
        acc.x += a.x; acc.y += a.y; acc.z += b.x; acc.w += b.y;
    }
    return acc;
}

// launch 3: layer-1 aggregation + relu -> fp16 X2
__global__ void k_agg_relu(const __half* __restrict__ hs, const float* __restrict__ bias,
                           __half* __restrict__ outh) {
    int d = blockIdx.x * (blockDim.x >> 5) + (threadIdx.x >> 5);
    int lane = threadIdx.x & 31;
    if (d >= NN) return;
    float4 acc = agg_row_h(hs, d, lane);
    float sc = g_dis[d];
    float4 bb = ((const float4*)bias)[lane];
    __half2 h0 = __floats2half2_rn(fmaxf(fmaf(sc, acc.x, bb.x), 0.f),
                                   fmaxf(fmaf(sc, acc.y, bb.y), 0.f));
    __half2 h1 = __floats2half2_rn(fmaxf(fmaf(sc, acc.z, bb.z), 0.f),
                                   fmaxf(fmaf(sc, acc.w, bb.w), 0.f));
    uint2 u;
    u.x = *reinterpret_cast<unsigned int*>(&h0);
    u.y = *reinterpret_cast<unsigned int*>(&h1);
    ((uint2*)outh)[d * 32 + lane] = u;
}

// launch 5: layer-2 aggregation + relu + mean-pool scatter
__global__ void k_agg_pool(const __half* __restrict__ hs, const float* __restrict__ bias) {
    int d = blockIdx.x * (blockDim.x >> 5) + (threadIdx.x >> 5);
    int lane = threadIdx.x & 31;
    if (d >= NN) return;
    float4 acc = agg_row_h(hs, d, lane);
    float sc = g_dis[d];
    float4 bb = ((const float4*)bias)[lane];
    float4 o;
    o.x = fmaxf(fmaf(sc, acc.x, bb.x), 0.f);
    o.y = fmaxf(fmaf(sc, acc.y, bb.y), 0.f);
    o.z = fmaxf(fmaf(sc, acc.z, bb.z), 0.f);
    o.w = fmaxf(fmaf(sc, acc.w, bb.w), 0.f);
    int g = g_bat[d];
    float* p = g_pool + g * C + lane * 4;
    atomicAdd(p + 0, o.x);
    atomicAdd(p + 1, o.y);
    atomicAdd(p + 2, o.z);
    atomicAdd(p + 3, o.w);
}

// launch 6: FC + log_softmax
__global__ void k_fc(const float* __restrict__ Wfc, const float* __restrict__ bfc,
                     float* __restrict__ out) {
    __shared__ float Wf[C * OC];
    int t = threadIdx.x;
    for (int i = t; i < C * OC; i += 128) Wf[i] = Wfc[i];
    __syncthreads();

    float inv = 1.0f / fmaxf((float)g_gcnt[t], 1.0f);
    float acc[OC];
#pragma unroll
    for (int j = 0; j < OC; j++) acc[j] = bfc[j];
    for (int k = 0; k < C; k++) {
        float p = g_pool[t * C + k] * inv;
#pragma unroll
        for (int j = 0; j < OC; j++) acc[j] += p * Wf[k * OC + j];
    }
    float m = acc[0];
#pragma unroll
    for (int j = 1; j < OC; j++) m = fmaxf(m, acc[j]);
    float sum = 0.f;
#pragma unroll
    for (int j = 0; j < OC; j++) sum += expf(acc[j] - m);
    float lse = m + logf(sum);
#pragma unroll
    for (int j = 0; j < OC; j++) out[t * OC + j] = acc[j] - lse;
}

extern "C" void kernel_launch(void* const* d_in, const int* in_sizes, int n_in,
                              void* d_out, int out_size) {
    const float* x     = (const float*)d_in[0];
    const void*  ei    = d_in[1];
    const void*  batch = d_in[2];
    const float* W1    = (const float*)d_in[3];
    const float* b1    = (const float*)d_in[4];
    const float* W2    = (const float*)d_in[5];
    const float* b2    = (const float*)d_in[6];
    const float* Wfc   = (const float*)d_in[7];
    const float* bfc   = (const float*)d_in[8];
    float* out = (float*)d_out;

    __half *Ah, *X2h;
    float *dis;
    cudaGetSymbolAddress((void**)&Ah,  g_Ah);
    cudaGetSymbolAddress((void**)&X2h, g_X2h);
    cudaGetSymbolAddress((void**)&dis, g_dis);

    size_t smem = (size_t)(128 + 64 + 64) * XS_STRIDE * sizeof(__half);   // 69632 B
    cudaFuncSetAttribute(k_gemm_fill, cudaFuncAttributeMaxDynamicSharedMemorySize, (int)smem);
    cudaFuncSetAttribute(k_gemm2, cudaFuncAttributeMaxDynamicSharedMemorySize, (int)smem);

    k_init<<<NBLK, 256>>>((const int*)ei);                    // 0
    k_scan_all<<<NBLK, 256>>>(ei, batch);                     // 1 (hist + barrier + scan)

    // Layer 1: persistent double-buffered HMMA gemm + CSR fill
    k_gemm_fill<<<PGEMM + FILL_BLKS, 256, smem>>>(x, W1, dis, Ah, ei); // 2
    k_agg_relu<<<(NN + 7) / 8, 256>>>(Ah, b1, X2h);           // 3 <- ncu lands here

    // Layer 2
    k_gemm2<<<PGEMM, 256, smem>>>(X2h, W2, dis, Ah);          // 4
    k_agg_pool<<<(NN + 7) / 8, 256>>>(Ah, b2);                // 5

    // Head
    k_fc<<<1, 128>>>(Wfc, bfc, out);                          // 6
}